// round 7
// baseline (speedup 1.0000x reference)
#include <cuda_runtime.h>
#include <cuda_bf16.h>

// out[b] = sum_k x[b,k] * |W[k]| * fc1_w[k] + fc1_b
// B=32, K = T*P = 4,000,000
#define NBATCH  32
#define TP      4000000
#define NVEC    (TP / 4)      // 1,000,000 float4 per batch row
#define GROUPS  18            // column groups  (R2's proven shape)
#define THREADS 256
#define NBLOCKS (NBATCH * GROUPS)    // 576
#define STRIDE  (GROUPS * THREADS)   // 4608 float4 per sweep

// Zero-at-exit scratch: zero at module load; finalizing block restores zero
// after each run -> deterministic across graph replays. No allocations.
__device__ float    g_partial[NBATCH];
__device__ unsigned g_count;

__global__ __launch_bounds__(THREADS, 4)
void dot_kernel(const float4* __restrict__ x,
                const float4* __restrict__ W,
                const float4* __restrict__ F,
                const float*  __restrict__ fc1_b,
                float* __restrict__ out) {
    const int b   = blockIdx.x & (NBATCH - 1);   // batch (fastest-varying)
    const int g   = blockIdx.x >> 5;             // column group 0..17
    const int tid = threadIdx.x;

    const float4* __restrict__ xb = x + (size_t)b * NVEC;

    float a0 = 0.f, a1 = 0.f, a2 = 0.f, a3 = 0.f;

#pragma unroll 4
    for (int j = g * THREADS + tid; j < NVEC; j += STRIDE) {
        // x: read-once 512MB stream -> evict-first so it can't thrash W/F
        float4 xv = __ldcs(&xb[j]);
        // W/F: shared across the 32 co-resident batch-blocks -> L2 hits
        //      (and L2-persistent across graph replays)
        float4 w = __ldg(&W[j]);
        float4 f = __ldg(&F[j]);
        a0 = fmaf(xv.x, fabsf(w.x) * f.x, a0);
        a1 = fmaf(xv.y, fabsf(w.y) * f.y, a1);
        a2 = fmaf(xv.z, fabsf(w.z) * f.z, a2);
        a3 = fmaf(xv.w, fabsf(w.w) * f.w, a3);
    }

    float v = (a0 + a1) + (a2 + a3);

    // ---- block reduction: warp shfl -> smem -> one atomic per block ----
    __shared__ float sred[THREADS / 32];
    const int lane = tid & 31;
    const int wrp  = tid >> 5;

#pragma unroll
    for (int off = 16; off; off >>= 1)
        v += __shfl_xor_sync(0xffffffffu, v, off);
    if (lane == 0) sred[wrp] = v;
    __syncthreads();

    if (tid == 0) {
        float s = 0.f;
#pragma unroll
        for (int w2 = 0; w2 < THREADS / 32; w2++) s += sred[w2];
        atomicAdd(&g_partial[b], s);
        __threadfence();
        unsigned t = atomicAdd(&g_count, 1u);
        if (t == NBLOCKS - 1) {
            // Last block finalizes and restores the scratch invariant.
            __threadfence();
            float bias = fc1_b[0];
#pragma unroll
            for (int i = 0; i < NBATCH; i++) {
                out[i] = g_partial[i] + bias;
                g_partial[i] = 0.0f;
            }
            g_count = 0u;
        }
    }
}

extern "C" void kernel_launch(void* const* d_in, const int* in_sizes, int n_in,
                              void* d_out, int out_size) {
    const float4* x  = (const float4*)d_in[0];  // [32, 4M]
    const float4* W  = (const float4*)d_in[1];  // [4M]
    const float4* F  = (const float4*)d_in[2];  // fc1_w [4M]
    const float*  bb = (const float*)d_in[3];   // fc1_b [1]
    float* out = (float*)d_out;                 // [32]

    (void)in_sizes; (void)n_in; (void)out_size;

    dot_kernel<<<NBLOCKS, THREADS>>>(x, W, F, bb, out);
}

// round 8
// speedup vs baseline: 1.1020x; 1.1020x over previous
#include <cuda_runtime.h>
#include <cuda_bf16.h>

// out[b] = sum_k x[b,k] * |W[k]| * fc1_w[k] + fc1_b
// B=32, K = T*P = 4,000,000
#define NBATCH  32
#define TP      4000000
#define NVEC    (TP / 4)      // 1,000,000 float4 per batch row
#define GROUPS  18            // column groups
#define THREADS 256
#define STRIDE  (GROUPS * THREADS)   // 4608 float4 per sweep

__global__ void init_out_kernel(const float* __restrict__ fc1_b,
                                float* __restrict__ out) {
    out[threadIdx.x] = fc1_b[0];
}

__global__ __launch_bounds__(THREADS, 4)
void dot_kernel(const float4* __restrict__ x,
                const float4* __restrict__ W,
                const float4* __restrict__ F,
                float* __restrict__ out) {
    const int b   = blockIdx.x & (NBATCH - 1);   // batch (fastest-varying)
    const int g   = blockIdx.x >> 5;             // column group 0..17
    const int tid = threadIdx.x;

    const float4* __restrict__ xb = x + (size_t)b * NVEC;

    float a0 = 0.f, a1 = 0.f, a2 = 0.f, a3 = 0.f;

#pragma unroll 4
    for (int j = g * THREADS + tid; j < NVEC; j += STRIDE) {
        // x: read-once stream -> evict-first so it can't thrash W/F in L2
        float4 xv = __ldcs(&xb[j]);
        // W/F: shared across the 32 co-resident batch-blocks -> L2 hits
        float4 w = __ldg(&W[j]);
        float4 f = __ldg(&F[j]);
        a0 = fmaf(xv.x, fabsf(w.x) * f.x, a0);
        a1 = fmaf(xv.y, fabsf(w.y) * f.y, a1);
        a2 = fmaf(xv.z, fabsf(w.z) * f.z, a2);
        a3 = fmaf(xv.w, fabsf(w.w) * f.w, a3);
    }

    float v = (a0 + a1) + (a2 + a3);

    // ---- block reduction: warp shfl -> smem -> single atomic ----
    __shared__ float sred[THREADS / 32];
    const int lane = tid & 31;
    const int wrp  = tid >> 5;

#pragma unroll
    for (int off = 16; off; off >>= 1)
        v += __shfl_xor_sync(0xffffffffu, v, off);
    if (lane == 0) sred[wrp] = v;
    __syncthreads();

    if (wrp == 0) {
        float s = (lane < THREADS / 32) ? sred[lane] : 0.f;
#pragma unroll
        for (int off = 4; off; off >>= 1)
            s += __shfl_xor_sync(0xffffffffu, s, off);
        if (lane == 0) atomicAdd(&out[b], s);
    }
}

extern "C" void kernel_launch(void* const* d_in, const int* in_sizes, int n_in,
                              void* d_out, int out_size) {
    const float4* x  = (const float4*)d_in[0];  // [32, 4M]
    const float4* W  = (const float4*)d_in[1];  // [4M]
    const float4* F  = (const float4*)d_in[2];  // fc1_w [4M]
    const float*  bb = (const float*)d_in[3];   // fc1_b [1]
    float* out = (float*)d_out;                 // [32]

    (void)in_sizes; (void)n_in; (void)out_size;

    init_out_kernel<<<1, NBATCH>>>(bb, out);
    dot_kernel<<<NBATCH * GROUPS, THREADS>>>(x, W, F, out);
}